// round 2
// baseline (speedup 1.0000x reference)
#include <cuda_runtime.h>
#include <cuda_bf16.h>
#include <stdint.h>

#define CIN   16
#define COUT  32
#define KK    27
#define TPB   256
#define MAX_H 300032
#define MAX_B 4096

// Scratch (no runtime allocation allowed)
__device__ float g_xt[MAX_H * CIN];          // transposed x: [h][c], 64B per row
__device__ float g_psum[MAX_B * COUT];       // per-block partial sums of y
__device__ float g_psq [MAX_B * COUT];       // per-block partial sums of y^2
__device__ float g_scale[COUT];
__device__ float g_shift[COUT];
__device__ int   g_is64;                     // neigh dtype flag (1 = int64)

// ---------------------------------------------------------------------------
// Kernel 0: detect neigh dtype. int32 data read as int64 gives huge values.
// ---------------------------------------------------------------------------
__global__ void detect_kernel(const long long* __restrict__ neigh,
                              int H, long long n_elems) {
    if (threadIdx.x != 0 || blockIdx.x != 0) return;
    long long n64 = n_elems / 2;               // 8-byte words available either way
    long long lim = n64 < 2048 ? n64 : 2048;
    int ok = 1;
    for (long long i = 0; i < lim; i++) {
        long long v = neigh[i];
        if (v < -1 || v >= (long long)H) { ok = 0; break; }
    }
    g_is64 = ok;
}

// ---------------------------------------------------------------------------
// Kernel 1: transpose x (C_IN, H) -> (H, C_IN) so each gather is 64B contiguous
// ---------------------------------------------------------------------------
__global__ void transpose_kernel(const float* __restrict__ x, int H) {
    int h = blockIdx.x * blockDim.x + threadIdx.x;
    if (h >= H) return;
    float v[CIN];
#pragma unroll
    for (int c = 0; c < CIN; c++) v[c] = x[(size_t)c * H + h];  // coalesced per c
    float4* dst = reinterpret_cast<float4*>(&g_xt[(size_t)h * CIN]);
#pragma unroll
    for (int j = 0; j < CIN / 4; j++)
        dst[j] = make_float4(v[4 * j], v[4 * j + 1], v[4 * j + 2], v[4 * j + 3]);
}

// ---------------------------------------------------------------------------
// Kernel 2: gather-conv. One thread per h, 32 fp32 accumulators.
// Weights staged in dynamic smem reordered to [k][o][i] (inner i contiguous ->
// LDS.128 broadcast). Also emits deterministic per-block partial sums for BN.
// ---------------------------------------------------------------------------
__global__ __launch_bounds__(TPB)
void conv_kernel(const float* __restrict__ w,
                 const void* __restrict__ neigh_raw,
                 float* __restrict__ out, int H) {
    extern __shared__ float ws[];                 // KK*COUT*CIN floats = 55.3 KB
    __shared__ float s_sum[TPB / 32][COUT];       // per-warp reduced sums
    __shared__ float s_sq [TPB / 32][COUT];

    // cooperative weight load + reorder: ws[k*512 + o*16 + i] = w[o,i,k]
    for (int idx = threadIdx.x; idx < KK * COUT * CIN; idx += TPB) {
        int k = idx / (COUT * CIN);
        int r = idx - k * (COUT * CIN);
        int o = r >> 4;
        int i = r & 15;
        ws[idx] = w[(o * CIN + i) * KK + k];
    }
    __syncthreads();

    const int is64 = g_is64;
    int h = blockIdx.x * TPB + threadIdx.x;
    float acc[COUT];
#pragma unroll
    for (int o = 0; o < COUT; o++) acc[o] = 0.0f;

    if (h < H) {
        // load this row's 27 indices into registers
        long long nidx[KK];
        if (is64) {
            const long long* nrow = (const long long*)neigh_raw + (long long)h * KK;
#pragma unroll
            for (int k = 0; k < KK; k++) nidx[k] = nrow[k];
        } else {
            const int* nrow = (const int*)neigh_raw + (long long)h * KK;
#pragma unroll
            for (int k = 0; k < KK; k++) nidx[k] = (long long)nrow[k];
        }

        for (int k = 0; k < KK; k++) {
            long long n = nidx[k];
            if (n >= 0 && n < (long long)H) {
                const float4* xp = reinterpret_cast<const float4*>(&g_xt[(size_t)n * CIN]);
                float4 a = xp[0], b = xp[1], c = xp[2], d = xp[3];
                float xv[CIN] = {a.x, a.y, a.z, a.w, b.x, b.y, b.z, b.w,
                                 c.x, c.y, c.z, c.w, d.x, d.y, d.z, d.w};
                const float* wk = &ws[k * COUT * CIN];
#pragma unroll
                for (int o = 0; o < COUT; o++) {
                    float s = acc[o];
#pragma unroll
                    for (int i = 0; i < CIN; i++)
                        s = fmaf(wk[o * CIN + i], xv[i], s);
                    acc[o] = s;
                }
            }
        }
        // write y (pre-BN) to d_out; coalesced per o across the warp
#pragma unroll
        for (int o = 0; o < COUT; o++) out[(size_t)o * H + h] = acc[o];
    }

    // --- deterministic block reduction of sum / sumsq per channel ---
    int lane = threadIdx.x & 31;
    int warp = threadIdx.x >> 5;
#pragma unroll
    for (int o = 0; o < COUT; o++) {
        float v  = acc[o];
        float v2 = v * v;
#pragma unroll
        for (int off = 16; off > 0; off >>= 1) {
            v  += __shfl_xor_sync(0xFFFFFFFFu, v,  off);
            v2 += __shfl_xor_sync(0xFFFFFFFFu, v2, off);
        }
        if (lane == 0) { s_sum[warp][o] = v; s_sq[warp][o] = v2; }
    }
    __syncthreads();
    if (threadIdx.x < COUT) {
        float S = 0.0f, Q = 0.0f;
#pragma unroll
        for (int wdx = 0; wdx < TPB / 32; wdx++) {
            S += s_sum[wdx][threadIdx.x];
            Q += s_sq [wdx][threadIdx.x];
        }
        g_psum[(size_t)blockIdx.x * COUT + threadIdx.x] = S;
        g_psq [(size_t)blockIdx.x * COUT + threadIdx.x] = Q;
    }
}

// ---------------------------------------------------------------------------
// Kernel 3: reduce partials -> scale/shift per channel (one block per channel)
// ---------------------------------------------------------------------------
__global__ void stats_kernel(const float* __restrict__ gamma,
                             const float* __restrict__ beta,
                             int H, int NB) {
    int o = blockIdx.x;
    float S = 0.0f, Q = 0.0f;
    for (int b = threadIdx.x; b < NB; b += blockDim.x) {
        S += g_psum[(size_t)b * COUT + o];
        Q += g_psq [(size_t)b * COUT + o];
    }
    __shared__ float ss[256], sq[256];
    ss[threadIdx.x] = S;
    sq[threadIdx.x] = Q;
    __syncthreads();
    for (int off = 128; off > 0; off >>= 1) {
        if (threadIdx.x < off) {
            ss[threadIdx.x] += ss[threadIdx.x + off];
            sq[threadIdx.x] += sq[threadIdx.x + off];
        }
        __syncthreads();
    }
    if (threadIdx.x == 0) {
        float invH = 1.0f / (float)H;
        float mean = ss[0] * invH;
        float var  = sq[0] * invH - mean * mean;
        float sc   = gamma[o] * rsqrtf(var + 1e-5f);
        g_scale[o] = sc;
        g_shift[o] = beta[o] - mean * sc;
    }
}

// ---------------------------------------------------------------------------
// Kernel 4: normalize in place
// ---------------------------------------------------------------------------
__global__ void norm_kernel(float* __restrict__ out, int H) {
    int o = blockIdx.y;
    int h = blockIdx.x * blockDim.x + threadIdx.x;
    if (h >= H) return;
    size_t idx = (size_t)o * H + h;
    out[idx] = out[idx] * g_scale[o] + g_shift[o];
}

// ---------------------------------------------------------------------------
extern "C" void kernel_launch(void* const* d_in, const int* in_sizes, int n_in,
                              void* d_out, int out_size) {
    const float* x     = (const float*)d_in[0];      // (1,16,H,1)
    const float* w     = (const float*)d_in[1];      // (32,16,27)
    const float* gamma = (const float*)d_in[2];      // (32,)
    const float* beta  = (const float*)d_in[3];      // (32,)
    const void*  neigh = d_in[4];                    // (H,27) int32 or int64

    int H  = in_sizes[0] / CIN;
    int NB = (H + TPB - 1) / TPB;
    long long n_neigh = (long long)in_sizes[4];

    static const int kWsmemBytes = KK * COUT * CIN * (int)sizeof(float);  // 55296
    cudaFuncSetAttribute(conv_kernel,
                         cudaFuncAttributeMaxDynamicSharedMemorySize, kWsmemBytes);

    detect_kernel<<<1, 1>>>((const long long*)neigh, H, n_neigh);
    transpose_kernel<<<(H + 255) / 256, 256>>>(x, H);
    conv_kernel<<<NB, TPB, kWsmemBytes>>>(w, neigh, (float*)d_out, H);
    stats_kernel<<<COUT, 256>>>(gamma, beta, H, NB);
    dim3 ngrid((H + 255) / 256, COUT);
    norm_kernel<<<ngrid, 256>>>((float*)d_out, H);
}

// round 3
// speedup vs baseline: 1.1088x; 1.1088x over previous
#include <cuda_runtime.h>
#include <cuda_bf16.h>
#include <stdint.h>

#define CIN   16
#define COUT  32
#define KK    27
#define TPB   256
#define MAX_H 300064
#define MAX_B 4096

// Scratch (no runtime allocation allowed)
__device__ float g_xt[(size_t)MAX_H * CIN];  // transposed x: [h][c], 64B/row; row H = zeros
__device__ float g_psum[MAX_B * COUT];       // per-block partial sums of y
__device__ float g_psq [MAX_B * COUT];       // per-block partial sums of y^2
__device__ float g_scale[COUT];
__device__ float g_shift[COUT];
__device__ int   g_is64;                     // neigh dtype flag (1 = int64)

// packed fp32x2 FMA: d.lo += a.lo*b.lo ; d.hi += a.hi*b.hi  (FFMA2 on sm_103a)
__device__ __forceinline__ void fma2(unsigned long long& d,
                                     unsigned long long a,
                                     unsigned long long b) {
    asm("fma.rn.f32x2 %0, %1, %2, %0;" : "+l"(d) : "l"(a), "l"(b));
}

// ---------------------------------------------------------------------------
// Kernel 0: detect neigh dtype (PARALLEL — previous serial version cost >100us)
// int32 data read as int64 gives values far outside [-1, H).
// ---------------------------------------------------------------------------
__global__ void detect_kernel(const long long* __restrict__ neigh,
                              int H, long long n_elems) {
    __shared__ int bad;
    if (threadIdx.x == 0) bad = 0;
    __syncthreads();
    long long n64 = n_elems / 2;               // 8-byte words safely readable either way
    long long lim = n64 < 4096 ? n64 : 4096;
    for (long long i = threadIdx.x; i < lim; i += blockDim.x) {
        long long v = neigh[i];
        if (v < -1 || v >= (long long)H) bad = 1;
    }
    __syncthreads();
    if (threadIdx.x == 0) g_is64 = (bad == 0);
}

// ---------------------------------------------------------------------------
// Kernel 1: transpose x (C_IN, H) -> (H, C_IN); pad rows [H, H+32) with zeros
// (invalid neighbors are redirected to row H -> contributes 0, no divergence)
// ---------------------------------------------------------------------------
__global__ void transpose_kernel(const float* __restrict__ x, int H) {
    int h = blockIdx.x * blockDim.x + threadIdx.x;
    float4* dst = reinterpret_cast<float4*>(&g_xt[(size_t)h * CIN]);
    if (h < H) {
        float v[CIN];
#pragma unroll
        for (int c = 0; c < CIN; c++) v[c] = x[(size_t)c * H + h];  // coalesced per c
#pragma unroll
        for (int j = 0; j < CIN / 4; j++)
            dst[j] = make_float4(v[4 * j], v[4 * j + 1], v[4 * j + 2], v[4 * j + 3]);
    } else if (h < H + 32 && h < MAX_H) {
        float4 z = make_float4(0.f, 0.f, 0.f, 0.f);
#pragma unroll
        for (int j = 0; j < CIN / 4; j++) dst[j] = z;
    }
}

// ---------------------------------------------------------------------------
// Kernel 2: gather-conv with packed f32x2 FMA.
// acc2[o].lo accumulates even-i terms, .hi odd-i terms; lo+hi at the end.
// x pairs and weight pairs are both naturally contiguous -> zero packing cost.
// ---------------------------------------------------------------------------
__global__ __launch_bounds__(TPB)
void conv_kernel(const float* __restrict__ w,
                 const void* __restrict__ neigh_raw,
                 float* __restrict__ out, int H) {
    extern __shared__ float ws[];                 // KK*COUT*CIN floats = 55.3 KB
    __shared__ float s_sum[TPB / 32][COUT];       // per-warp reduced sums
    __shared__ float s_sq [TPB / 32][COUT];

    // cooperative weight load + reorder: ws[k*512 + o*16 + i] = w[o,i,k]
    for (int idx = threadIdx.x; idx < KK * COUT * CIN; idx += TPB) {
        int k = idx / (COUT * CIN);
        int r = idx - k * (COUT * CIN);
        int o = r >> 4;
        int i = r & 15;
        ws[idx] = w[(o * CIN + i) * KK + k];
    }
    __syncthreads();

    const int is64 = g_is64;
    int h = blockIdx.x * TPB + threadIdx.x;
    bool active = h < H;

    unsigned long long acc2[COUT];
#pragma unroll
    for (int o = 0; o < COUT; o++) acc2[o] = 0ULL;

    if (active) {
        // load this row's 27 indices; invalid (<0 or >=H) -> zero pad row H
        int nidx[KK];
        if (is64) {
            const long long* nrow = (const long long*)neigh_raw + (long long)h * KK;
#pragma unroll
            for (int k = 0; k < KK; k++) {
                long long v = nrow[k];
                nidx[k] = (v < 0 || v >= (long long)H) ? H : (int)v;
            }
        } else {
            const int* nrow = (const int*)neigh_raw + (long long)h * KK;
#pragma unroll
            for (int k = 0; k < KK; k++) {
                int v = nrow[k];
                nidx[k] = ((unsigned)v >= (unsigned)H) ? H : v;
            }
        }

        for (int k = 0; k < KK; k++) {
            const ulonglong2* xp =
                reinterpret_cast<const ulonglong2*>(&g_xt[(size_t)nidx[k] * CIN]);
            ulonglong2 xa = xp[0], xb = xp[1], xc = xp[2], xd = xp[3];
            unsigned long long xq[8] = {xa.x, xa.y, xb.x, xb.y,
                                        xc.x, xc.y, xd.x, xd.y};
            const ulonglong2* wk =
                reinterpret_cast<const ulonglong2*>(&ws[k * COUT * CIN]);
#pragma unroll
            for (int o = 0; o < COUT; o++) {
                ulonglong2 w0 = wk[o * 4 + 0];
                ulonglong2 w1 = wk[o * 4 + 1];
                ulonglong2 w2 = wk[o * 4 + 2];
                ulonglong2 w3 = wk[o * 4 + 3];
                fma2(acc2[o], xq[0], w0.x);
                fma2(acc2[o], xq[1], w0.y);
                fma2(acc2[o], xq[2], w1.x);
                fma2(acc2[o], xq[3], w1.y);
                fma2(acc2[o], xq[4], w2.x);
                fma2(acc2[o], xq[5], w2.y);
                fma2(acc2[o], xq[6], w3.x);
                fma2(acc2[o], xq[7], w3.y);
            }
        }
    }

    // reduce lo+hi -> scalar accumulators
    float acc[COUT];
#pragma unroll
    for (int o = 0; o < COUT; o++) {
        float2 p = *reinterpret_cast<float2*>(&acc2[o]);
        acc[o] = p.x + p.y;
    }

    if (active) {
#pragma unroll
        for (int o = 0; o < COUT; o++) out[(size_t)o * H + h] = acc[o];
    }

    // --- deterministic block reduction of sum / sumsq per channel ---
    int lane = threadIdx.x & 31;
    int warp = threadIdx.x >> 5;
#pragma unroll
    for (int o = 0; o < COUT; o++) {
        float v  = active ? acc[o] : 0.0f;
        float v2 = v * v;
#pragma unroll
        for (int off = 16; off > 0; off >>= 1) {
            v  += __shfl_xor_sync(0xFFFFFFFFu, v,  off);
            v2 += __shfl_xor_sync(0xFFFFFFFFu, v2, off);
        }
        if (lane == 0) { s_sum[warp][o] = v; s_sq[warp][o] = v2; }
    }
    __syncthreads();
    if (threadIdx.x < COUT) {
        float S = 0.0f, Q = 0.0f;
#pragma unroll
        for (int wdx = 0; wdx < TPB / 32; wdx++) {
            S += s_sum[wdx][threadIdx.x];
            Q += s_sq [wdx][threadIdx.x];
        }
        g_psum[(size_t)blockIdx.x * COUT + threadIdx.x] = S;
        g_psq [(size_t)blockIdx.x * COUT + threadIdx.x] = Q;
    }
}

// ---------------------------------------------------------------------------
// Kernel 3: reduce partials -> scale/shift per channel (one block per channel)
// ---------------------------------------------------------------------------
__global__ void stats_kernel(const float* __restrict__ gamma,
                             const float* __restrict__ beta,
                             int H, int NB) {
    int o = blockIdx.x;
    float S = 0.0f, Q = 0.0f;
    for (int b = threadIdx.x; b < NB; b += blockDim.x) {
        S += g_psum[(size_t)b * COUT + o];
        Q += g_psq [(size_t)b * COUT + o];
    }
    __shared__ float ss[256], sq[256];
    ss[threadIdx.x] = S;
    sq[threadIdx.x] = Q;
    __syncthreads();
    for (int off = 128; off > 0; off >>= 1) {
        if (threadIdx.x < off) {
            ss[threadIdx.x] += ss[threadIdx.x + off];
            sq[threadIdx.x] += sq[threadIdx.x + off];
        }
        __syncthreads();
    }
    if (threadIdx.x == 0) {
        float invH = 1.0f / (float)H;
        float mean = ss[0] * invH;
        float var  = sq[0] * invH - mean * mean;
        float sc   = gamma[o] * rsqrtf(var + 1e-5f);
        g_scale[o] = sc;
        g_shift[o] = beta[o] - mean * sc;
    }
}

// ---------------------------------------------------------------------------
// Kernel 4: normalize in place (float4 vectorized)
// ---------------------------------------------------------------------------
__global__ void norm_kernel(float* __restrict__ out, int H) {
    int o = blockIdx.y;
    int i = blockIdx.x * blockDim.x + threadIdx.x;
    int H4 = H >> 2;
    float sc = g_scale[o], sh = g_shift[o];
    float4* p = reinterpret_cast<float4*>(out + (size_t)o * H);
    if (i < H4) {
        float4 v = p[i];
        v.x = v.x * sc + sh;
        v.y = v.y * sc + sh;
        v.z = v.z * sc + sh;
        v.w = v.w * sc + sh;
        p[i] = v;
    }
    // scalar tail (H % 4 elements)
    if (blockIdx.x == 0 && threadIdx.x < (H & 3)) {
        int hh = H4 * 4 + threadIdx.x;
        out[(size_t)o * H + hh] = out[(size_t)o * H + hh] * sc + sh;
    }
}

// ---------------------------------------------------------------------------
extern "C" void kernel_launch(void* const* d_in, const int* in_sizes, int n_in,
                              void* d_out, int out_size) {
    const float* x     = (const float*)d_in[0];      // (1,16,H,1)
    const float* w     = (const float*)d_in[1];      // (32,16,27)
    const float* gamma = (const float*)d_in[2];      // (32,)
    const float* beta  = (const float*)d_in[3];      // (32,)
    const void*  neigh = d_in[4];                    // (H,27) int32 or int64

    int H  = in_sizes[0] / CIN;
    int NB = (H + TPB - 1) / TPB;
    long long n_neigh = (long long)in_sizes[4];

    static const int kWsmemBytes = KK * COUT * CIN * (int)sizeof(float);  // 55296
    cudaFuncSetAttribute(conv_kernel,
                         cudaFuncAttributeMaxDynamicSharedMemorySize, kWsmemBytes);

    detect_kernel<<<1, 256>>>((const long long*)neigh, H, n_neigh);
    transpose_kernel<<<(H + 32 + 255) / 256, 256>>>(x, H);
    conv_kernel<<<NB, TPB, kWsmemBytes>>>(w, neigh, (float*)d_out, H);
    stats_kernel<<<COUT, 256>>>(gamma, beta, H, NB);
    dim3 ngrid((H / 4 + 255) / 256, COUT);
    norm_kernel<<<ngrid, 256>>>((float*)d_out, H);
}